// round 7
// baseline (speedup 1.0000x reference)
#include <cuda_runtime.h>
#include <cstdint>

// Shapes (fixed):
//   W: [D=1024, ML=8192] row-major, b: [D=1024]
//   out: [B=4, S=4096, D=1024] = broadcast_B( W[:, :S].T + b )
#define B_DIM 4
#define S_DIM 4096
#define D_DIM 1024
#define ML_DIM 8192

#define S_CHUNK 8
#define D_CHUNK 512
#define ROWF (D_CHUNK + 4)   // 516 floats/row: STS bank=(16j+4k+d)%32 CF; rows 16B-aligned
#define THREADS 256

__device__ __forceinline__ uint32_t smem_u32(const void* p) {
    uint32_t a;
    asm("{ .reg .u64 t; cvta.to.shared.u64 t, %1; cvt.u32.u64 %0, t; }"
        : "=r"(a) : "l"(p));
    return a;
}

// CTA = 8s x 512d tile. Produce transposed+biased tile in smem (coalesced
// 32B-per-row LDG, conflict-free STS), then 32 async 2KB bulk stores
// (8 s-rows x 4 batch copies) on the TMA path; wait only before exit.
__global__ void __launch_bounds__(THREADS)
posemb_v7(const float4* __restrict__ W4,
          const float* __restrict__ bias,
          float* __restrict__ out) {
    __shared__ __align__(16) float tile[S_CHUNK * ROWF];  // 16,512 B

    const int t  = threadIdx.x;
    const int s0 = blockIdx.x * S_CHUNK;
    const int d0 = blockIdx.y * D_CHUNK;

    // 1024 tasks: tau -> (dl = tau>>1, j = tau&1). Lane pairs read 32B
    // contiguous from one W row (full-sector reads, 16 lines/warp-inst).
    float4 w[4];
    float  bv[4];
#pragma unroll
    for (int p = 0; p < 4; p++) {
        const int tau = t + THREADS * p;
        const int dl  = tau >> 1;
        const int j   = tau & 1;
        w[p]  = __ldg(&W4[(size_t)(d0 + dl) * (ML_DIM / 4) + (s0 >> 2) + j]);
        bv[p] = __ldg(&bias[d0 + dl]);
    }
#pragma unroll
    for (int p = 0; p < 4; p++) {
        const int tau = t + THREADS * p;
        const int dl  = tau >> 1;
        const int sb  = 4 * (tau & 1);
        tile[(sb + 0) * ROWF + dl] = w[p].x + bv[p];
        tile[(sb + 1) * ROWF + dl] = w[p].y + bv[p];
        tile[(sb + 2) * ROWF + dl] = w[p].z + bv[p];
        tile[(sb + 3) * ROWF + dl] = w[p].w + bv[p];
    }
    __syncthreads();

    // 32 threads each issue one 2KB bulk store: row s (0..7) x batch b (0..3).
    if (t < S_CHUNK * B_DIM) {
        asm volatile("fence.proxy.async.shared::cta;" ::: "memory");

        const int s = t >> 2;
        const int b = t & 3;

        const uint32_t src = smem_u32(&tile[s * ROWF]);
        float* dst = out + (size_t)(b * S_DIM + s0 + s) * D_DIM + d0;

        asm volatile(
            "cp.async.bulk.global.shared::cta.bulk_group [%0], [%1], %2;"
            :: "l"(dst), "r"(src), "n"(D_CHUNK * 4)
            : "memory");
        asm volatile("cp.async.bulk.commit_group;" ::: "memory");
        // Drain before CTA exit (smem reuse safety). Overlap comes from
        // the ~7 concurrent CTAs per SM, not from within this CTA.
        asm volatile("cp.async.bulk.wait_group 0;" ::: "memory");
    }
}

extern "C" void kernel_launch(void* const* d_in, const int* in_sizes, int n_in,
                              void* d_out, int out_size) {
    (void)in_sizes; (void)n_in; (void)out_size;
    const float4* W4   = (const float4*)d_in[1];
    const float*  bias = (const float*)d_in[2];
    float*        out  = (float*)d_out;

    dim3 block(THREADS);
    dim3 grid(S_DIM / S_CHUNK, D_DIM / D_CHUNK);  // 512 x 2 = 1024 CTAs
    posemb_v7<<<grid, block>>>(W4, bias, out);
}

// round 8
// speedup vs baseline: 1.1577x; 1.1577x over previous
#include <cuda_runtime.h>

// Shapes (fixed):
//   W: [D=1024, ML=8192] row-major, b: [D=1024]
//   out: [B=4, S=4096, D=1024] = broadcast_B( W[:, :S].T + b )
#define B_DIM 4
#define S_DIM 4096
#define D_DIM 1024
#define ML_DIM 8192

#define TROW 33  // stride 33: STS bank=(4s4+k+drow)%32, LDS bank=(sl+4dg+j)%32 -> conflict-free

// 32s x 32d tile per CTA, 256 threads, 4096 CTAs (proven best structure).
// Load : thread (drow=t>>3, s4=t&7): one LDG.128 W[d0+drow][s0+4*s4 ..+3]
//        -> 4 scalar STS into tile[s][drow]   (conflict-free)
// Store: thread (sl=t>>3, dg=t&7): 4 scalar LDS tile[sl][4dg..+3] (CF)
//        -> float4 + bias -> 4 coalesced STG.128 (one per batch copy).
__global__ void __launch_bounds__(256)
posemb_v8(const float4* __restrict__ W4,
          const float4* __restrict__ bias4,
          float4* __restrict__ out4) {
    __shared__ float tile[32 * TROW];

    const int t  = threadIdx.x;
    const int s0 = blockIdx.x * 32;
    const int d0 = blockIdx.y * 32;

    const int drow = t >> 3;   // 0..31 (d within tile)
    const int s4   = t & 7;    // 0..7  (float4 index along s)
    const int dg   = t & 7;    // 0..7  (float4 group along d, store phase)
    const int sl   = t >> 3;   // 0..31 (s within tile, store phase)

    // Hoist bias off the post-barrier critical path.
    const float4 bb = __ldg(&bias4[(d0 >> 2) + dg]);

    const float4 w = __ldg(&W4[(size_t)(d0 + drow) * (ML_DIM / 4) + (s0 >> 2) + s4]);

    const int sb = 4 * s4;
    tile[(sb + 0) * TROW + drow] = w.x;
    tile[(sb + 1) * TROW + drow] = w.y;
    tile[(sb + 2) * TROW + drow] = w.z;
    tile[(sb + 3) * TROW + drow] = w.w;

    __syncthreads();

    const float* row = &tile[sl * TROW + 4 * dg];
    float4 v;
    v.x = row[0] + bb.x;
    v.y = row[1] + bb.y;
    v.z = row[2] + bb.z;
    v.w = row[3] + bb.w;

    // Single base + stride-adds for the four replicated batch streams.
    const size_t batch_stride = (size_t)S_DIM * (D_DIM / 4);
    float4* p = out4 + (size_t)(s0 + sl) * (D_DIM / 4) + (d0 >> 2) + dg;

    p[0]                = v;
    p[batch_stride]     = v;
    p[2 * batch_stride] = v;
    p[3 * batch_stride] = v;
}

extern "C" void kernel_launch(void* const* d_in, const int* in_sizes, int n_in,
                              void* d_out, int out_size) {
    (void)in_sizes; (void)n_in; (void)out_size;
    const float4* W4    = (const float4*)d_in[1];
    const float4* bias4 = (const float4*)d_in[2];
    float4* out4        = (float4*)d_out;

    dim3 block(256);
    dim3 grid(S_DIM / 32, D_DIM / 32);  // 128 x 32 = 4096 CTAs
    posemb_v8<<<grid, block>>>(W4, bias4, out4);
}